// round 3
// baseline (speedup 1.0000x reference)
#include <cuda_runtime.h>

#define TPB   256
#define DIM   4096
#define KSEL  409
#define MAXC  512
#define NWARP (TPB / 32)

// Per-row exact top-k threshold via register-resident bisection + small select,
// fused with sigmoid masking. One CTA per row of 4096 fp32.
__global__ __launch_bounds__(TPB) void sparsify_kernel(const float* __restrict__ x,
                                                       float* __restrict__ out) {
    __shared__ float s_wredf[NWARP];
    __shared__ int   s_wcnt[NWARP];
    __shared__ float s_cand[MAXC];
    __shared__ int   s_num;
    __shared__ float s_thr;

    const int t    = threadIdx.x;
    const int lane = t & 31;
    const int wid  = t >> 5;

    const float4* xr   = reinterpret_cast<const float4*>(x + (size_t)blockIdx.x * DIM);
    float4*       orow = reinterpret_cast<float4*>(out + (size_t)blockIdx.x * DIM);

    // 16 elements per thread, coalesced float4 loads
    float4 v0 = xr[t];
    float4 v1 = xr[t + TPB];
    float4 v2 = xr[t + 2 * TPB];
    float4 v3 = xr[t + 3 * TPB];

    // ---- block max(|x|) ----
    float m = fabsf(v0.x);
    m = fmaxf(m, fabsf(v0.y)); m = fmaxf(m, fabsf(v0.z)); m = fmaxf(m, fabsf(v0.w));
    m = fmaxf(m, fabsf(v1.x)); m = fmaxf(m, fabsf(v1.y)); m = fmaxf(m, fabsf(v1.z)); m = fmaxf(m, fabsf(v1.w));
    m = fmaxf(m, fabsf(v2.x)); m = fmaxf(m, fabsf(v2.y)); m = fmaxf(m, fabsf(v2.z)); m = fmaxf(m, fabsf(v2.w));
    m = fmaxf(m, fabsf(v3.x)); m = fmaxf(m, fabsf(v3.y)); m = fmaxf(m, fabsf(v3.z)); m = fmaxf(m, fabsf(v3.w));
    #pragma unroll
    for (int o = 16; o; o >>= 1) m = fmaxf(m, __shfl_xor_sync(0xFFFFFFFFu, m, o));
    if (lane == 0) s_wredf[wid] = m;
    __syncthreads();
    float maxv = s_wredf[0];
    #pragma unroll
    for (int w = 1; w < NWARP; w++) maxv = fmaxf(maxv, s_wredf[w]);
    __syncthreads();

    // count(|x| > thr) over the whole block (all threads return the same total)
    auto countAbove = [&](float thr) -> int {
        int c = 0;
        c += fabsf(v0.x) > thr; c += fabsf(v0.y) > thr; c += fabsf(v0.z) > thr; c += fabsf(v0.w) > thr;
        c += fabsf(v1.x) > thr; c += fabsf(v1.y) > thr; c += fabsf(v1.z) > thr; c += fabsf(v1.w) > thr;
        c += fabsf(v2.x) > thr; c += fabsf(v2.y) > thr; c += fabsf(v2.z) > thr; c += fabsf(v2.w) > thr;
        c += fabsf(v3.x) > thr; c += fabsf(v3.y) > thr; c += fabsf(v3.z) > thr; c += fabsf(v3.w) > thr;
        #pragma unroll
        for (int o = 16; o; o >>= 1) c += __shfl_xor_sync(0xFFFFFFFFu, c, o);
        if (lane == 0) s_wcnt[wid] = c;
        __syncthreads();
        int tot = 0;
        #pragma unroll
        for (int w = 0; w < NWARP; w++) tot += s_wcnt[w];
        __syncthreads();
        return tot;
    };

    // ---- value-space bisection: invariant count(>lo) >= K, count(>hi) < K ----
    float lo = -1.0f, hi = maxv;
    int cLo = DIM;     // all |x| >= 0 > -1
    int cHi = 0;       // count(|x| > maxv) == 0
    int iter = 0;
    while ((cLo - cHi) > 64 && iter < 48) {
        float mid = 0.5f * (lo + hi);
        if (mid == lo || mid == hi) break;   // degenerate interval
        int c = countAbove(mid);
        if (c >= KSEL) { lo = mid; cLo = c; }
        else           { hi = mid; cHi = c; }
        iter++;
    }

    // ---- gather candidates in (lo, hi] ----
    if (t == 0) s_num = 0;
    __syncthreads();
    {
        float av;
        #define TRY_CAND(e) \
            av = fabsf(e); \
            if (av > lo && av <= hi) { int id = atomicAdd(&s_num, 1); if (id < MAXC) s_cand[id] = av; }
        TRY_CAND(v0.x) TRY_CAND(v0.y) TRY_CAND(v0.z) TRY_CAND(v0.w)
        TRY_CAND(v1.x) TRY_CAND(v1.y) TRY_CAND(v1.z) TRY_CAND(v1.w)
        TRY_CAND(v2.x) TRY_CAND(v2.y) TRY_CAND(v2.z) TRY_CAND(v2.w)
        TRY_CAND(v3.x) TRY_CAND(v3.y) TRY_CAND(v3.z) TRY_CAND(v3.w)
        #undef TRY_CAND
    }
    __syncthreads();

    // ---- exact select: need-th largest among candidates ----
    const int c    = min(s_num, MAXC);
    const int need = KSEL - cHi;           // 1-based rank within candidates
    for (int j = t; j < c; j += TPB) {
        float vj = s_cand[j];
        int gt = 0, ge = 0;
        for (int i = 0; i < c; i++) {
            float vi = s_cand[i];
            gt += vi > vj;
            ge += vi >= vj;
        }
        if (gt < need && need <= ge) s_thr = vj;   // all matching writers write same value
    }
    __syncthreads();
    const float thr = s_thr;
    const float nthr10 = -10.0f * thr;

    // ---- fused epilogue: out = x * sigmoid(10*(|x| - thr)) ----
    auto mask1 = [&](float xv) -> float {
        float z = fmaf(10.0f, fabsf(xv), nthr10);
        float e = __expf(-z);
        return xv * __fdividef(1.0f, 1.0f + e);
    };
    float4 o0, o1, o2, o3;
    o0.x = mask1(v0.x); o0.y = mask1(v0.y); o0.z = mask1(v0.z); o0.w = mask1(v0.w);
    o1.x = mask1(v1.x); o1.y = mask1(v1.y); o1.z = mask1(v1.z); o1.w = mask1(v1.w);
    o2.x = mask1(v2.x); o2.y = mask1(v2.y); o2.z = mask1(v2.z); o2.w = mask1(v2.w);
    o3.x = mask1(v3.x); o3.y = mask1(v3.y); o3.z = mask1(v3.z); o3.w = mask1(v3.w);
    orow[t]            = o0;
    orow[t + TPB]      = o1;
    orow[t + 2 * TPB]  = o2;
    orow[t + 3 * TPB]  = o3;
}

extern "C" void kernel_launch(void* const* d_in, const int* in_sizes, int n_in,
                              void* d_out, int out_size) {
    const float* x = (const float*)d_in[0];
    float* out = (float*)d_out;
    const int rows = in_sizes[0] / DIM;   // 4 * 2048 = 8192 rows of 4096
    sparsify_kernel<<<rows, TPB>>>(x, out);
}

// round 5
// speedup vs baseline: 1.0253x; 1.0253x over previous
#include <cuda_runtime.h>

#define TPB   256
#define DIM   4096
#define KSEL  409
#define MAXC  512
#define NWARP (TPB / 32)

// Static anchors for N(0,1)-like data: P(|x|>1.45)~0.147 (~602 counts),
// P(|x|>1.90)~0.057 (~235 counts). Rank 409 lies between with ~10 sigma margin.
// Any distribution that violates this just falls into the general refinement loop.
#define LO_A 1.45f
#define HI_A 1.90f

__global__ __launch_bounds__(TPB) void sparsify_kernel(const float* __restrict__ x,
                                                       float* __restrict__ out) {
    __shared__ unsigned s_pack[2][NWARP];
    __shared__ float    s_wmax[NWARP];
    __shared__ float    s_cand[MAXC];
    __shared__ int      s_num;
    __shared__ float    s_thr;

    const int t    = threadIdx.x;
    const int lane = t & 31;
    const int wid  = t >> 5;

    const float4* xr   = reinterpret_cast<const float4*>(x + (size_t)blockIdx.x * DIM);
    float4*       orow = reinterpret_cast<float4*>(out + (size_t)blockIdx.x * DIM);

    // 16 elements per thread, coalesced float4 loads
    float4 v0 = xr[t];
    float4 v1 = xr[t + TPB];
    float4 v2 = xr[t + 2 * TPB];
    float4 v3 = xr[t + 3 * TPB];

    if (t == 0) s_num = 0;   // ordered by the first barrier below

    // packed dual-threshold count over this thread's 16 elements:
    // high 16 bits: count(|x| > ta), low 16 bits: count(|x| > tb)
    auto pack16 = [&](float ta, float tb) -> unsigned {
        unsigned p = 0;
        #define CC(e) { float av = fabsf(e); if (av > ta) p += 65536u; if (av > tb) p += 1u; }
        CC(v0.x) CC(v0.y) CC(v0.z) CC(v0.w)
        CC(v1.x) CC(v1.y) CC(v1.z) CC(v1.w)
        CC(v2.x) CC(v2.y) CC(v2.z) CC(v2.w)
        CC(v3.x) CC(v3.y) CC(v3.z) CC(v3.w)
        #undef CC
        return p;
    };

    int phase = 0;

    // ---- stage A: block max(|x|) + counts at static anchors, ONE barrier ----
    float m = fabsf(v0.x);
    m = fmaxf(m, fabsf(v0.y)); m = fmaxf(m, fabsf(v0.z)); m = fmaxf(m, fabsf(v0.w));
    m = fmaxf(m, fabsf(v1.x)); m = fmaxf(m, fabsf(v1.y)); m = fmaxf(m, fabsf(v1.z)); m = fmaxf(m, fabsf(v1.w));
    m = fmaxf(m, fabsf(v2.x)); m = fmaxf(m, fabsf(v2.y)); m = fmaxf(m, fabsf(v2.z)); m = fmaxf(m, fabsf(v2.w));
    m = fmaxf(m, fabsf(v3.x)); m = fmaxf(m, fabsf(v3.y)); m = fmaxf(m, fabsf(v3.z)); m = fmaxf(m, fabsf(v3.w));
    #pragma unroll
    for (int o = 16; o; o >>= 1) m = fmaxf(m, __shfl_xor_sync(0xFFFFFFFFu, m, o));

    unsigned pA = __reduce_add_sync(0xFFFFFFFFu, pack16(LO_A, HI_A));
    if (lane == 0) { s_pack[0][wid] = pA; s_wmax[wid] = m; }
    __syncthreads();
    unsigned totA = 0; float maxv = s_wmax[0];
    #pragma unroll
    for (int w = 0; w < NWARP; w++) { totA += s_pack[0][w]; maxv = fmaxf(maxv, s_wmax[w]); }
    phase = 1;
    const int cA_lo = (int)(totA >> 16), cA_hi = (int)(totA & 0xFFFFu);

    // block-wide dual count with double-buffered smem (one barrier per call)
    auto blockCount2 = [&](float ta, float tb, int& ca, int& cb) {
        unsigned p = __reduce_add_sync(0xFFFFFFFFu, pack16(ta, tb));
        int buf = phase & 1;
        if (lane == 0) s_pack[buf][wid] = p;
        __syncthreads();
        unsigned tot = 0;
        #pragma unroll
        for (int w = 0; w < NWARP; w++) tot += s_pack[buf][w];
        phase++;
        ca = (int)(tot >> 16); cb = (int)(tot & 0xFFFFu);
    };

    // ---- bracket init: invariant count(>lo)=cLo >= K > cHi=count(>hi) ----
    float lo, hi; int cLo, cHi;
    if (cA_hi >= KSEL)      { lo = HI_A;  cLo = cA_hi; hi = maxv; cHi = 0; }
    else if (cA_lo >= KSEL) { lo = LO_A;  cLo = cA_lo; hi = HI_A; cHi = cA_hi; }
    else                    { lo = -1.0f; cLo = DIM;   hi = LO_A; cHi = cA_lo; }

    // ---- refinement: exponential-CDF interpolation (usually 1 iteration) ----
    int guard = 0;
    while ((cLo - cHi) > 128 && guard < 24 && lo < hi) {
        float span = hi - lo;
        float dens = (float)(cLo - cHi) / span;     // candidates per unit value
        float chg  = (float)(cHi > 0 ? cHi : 1);
        float lam  = __logf((float)cLo / chg) / span;
        float t1   = (lam > 1e-20f) ? (lo + __logf((float)cLo / (float)KSEL) / lam)
                                    : (0.5f * (lo + hi));
        float dv   = 48.0f / dens;                  // +-48 expected counts
        float blo = t1 - dv, bhi = t1 + dv;
        if (!(blo > lo)) blo = lo + 0.25f * span;
        if (!(bhi < hi)) bhi = hi - 0.25f * span;
        if (!(blo < bhi)) { blo = lo + 0.333f * span; bhi = lo + 0.667f * span; }
        int c1, c2;
        blockCount2(blo, bhi, c1, c2);              // c1 >= c2
        if (c2 >= KSEL)      { lo = bhi; cLo = c2; }
        else if (c1 >= KSEL) { lo = blo; cLo = c1; hi = bhi; cHi = c2; }
        else                 { hi = blo; cHi = c1; }
        guard++;
    }

    // ---- gather candidates in (lo, hi] ----
    if (t == 0) s_thr = hi;   // default (always overwritten in valid cases)
    {
        float av;
        #define TRY_CAND(e) \
            av = fabsf(e); \
            if (av > lo && av <= hi) { int id = atomicAdd(&s_num, 1); if (id < MAXC) s_cand[id] = av; }
        TRY_CAND(v0.x) TRY_CAND(v0.y) TRY_CAND(v0.z) TRY_CAND(v0.w)
        TRY_CAND(v1.x) TRY_CAND(v1.y) TRY_CAND(v1.z) TRY_CAND(v1.w)
        TRY_CAND(v2.x) TRY_CAND(v2.y) TRY_CAND(v2.z) TRY_CAND(v2.w)
        TRY_CAND(v3.x) TRY_CAND(v3.y) TRY_CAND(v3.z) TRY_CAND(v3.w)
        #undef TRY_CAND
    }
    __syncthreads();

    // ---- exact select: need-th largest among candidates (c <= ~128) ----
    const int c    = min(s_num, MAXC);
    const int need = KSEL - cHi;                   // 1-based rank within candidates
    for (int j = t; j < c; j += TPB) {
        float vj = s_cand[j];
        int gt = 0, ge = 0;
        for (int i = 0; i < c; i++) {
            float vi = s_cand[i];                  // smem broadcast
            gt += vi > vj;
            ge += vi >= vj;
        }
        if (gt < need && need <= ge) s_thr = vj;   // all matching writers write same value
    }
    __syncthreads();
    const float thr = s_thr;
    const float nthr10 = -10.0f * thr;

    // ---- fused epilogue: out = x * sigmoid(10*(|x| - thr)) ----
    auto mask1 = [&](float xv) -> float {
        float z = fmaf(10.0f, fabsf(xv), nthr10);
        float e = __expf(-z);
        return xv * __fdividef(1.0f, 1.0f + e);
    };
    float4 o0, o1, o2, o3;
    o0.x = mask1(v0.x); o0.y = mask1(v0.y); o0.z = mask1(v0.z); o0.w = mask1(v0.w);
    o1.x = mask1(v1.x); o1.y = mask1(v1.y); o1.z = mask1(v1.z); o1.w = mask1(v1.w);
    o2.x = mask1(v2.x); o2.y = mask1(v2.y); o2.z = mask1(v2.z); o2.w = mask1(v2.w);
    o3.x = mask1(v3.x); o3.y = mask1(v3.y); o3.z = mask1(v3.z); o3.w = mask1(v3.w);
    orow[t]           = o0;
    orow[t + TPB]     = o1;
    orow[t + 2 * TPB] = o2;
    orow[t + 3 * TPB] = o3;
}

extern "C" void kernel_launch(void* const* d_in, const int* in_sizes, int n_in,
                              void* d_out, int out_size) {
    const float* x = (const float*)d_in[0];
    float* out = (float*)d_out;
    const int rows = in_sizes[0] / DIM;   // 4 * 2048 = 8192 rows of 4096
    sparsify_kernel<<<rows, TPB>>>(x, out);
}

// round 6
// speedup vs baseline: 1.3446x; 1.3114x over previous
#include <cuda_runtime.h>

#define TPB    256
#define DIM    4096
#define KSEL   409
#define MAXC   512
#define NWARP  (TPB / 32)
#define SMALLC 48

// Static anchors for N(0,1)-like rows: P(|x|>1.495)~0.135 (~553), P(|x|>1.795)~0.0727 (~298).
// Rank 409 lies inside with ~3.3 sigma margin; window holds ~255 candidates (< MAXC).
// Rows violating this take the generic bisection fallback (exact for any data).
#define BLO_A 1.495f
#define BHI_A 1.795f

__global__ __launch_bounds__(TPB) void sparsify_kernel(const float* __restrict__ x,
                                                       float* __restrict__ out) {
    __shared__ unsigned s_pack[NWARP];
    __shared__ float    s_wmax[NWARP];
    __shared__ float    s_buf[2][MAXC];
    __shared__ int      s_cnt[2];
    __shared__ int      s_hist[32];
    __shared__ int      s_selbin, s_need;
    __shared__ float    s_thr;

    const int t    = threadIdx.x;
    const int lane = t & 31;
    const int wid  = t >> 5;

    const float4* xr   = reinterpret_cast<const float4*>(x + (size_t)blockIdx.x * DIM);
    float4*       orow = reinterpret_cast<float4*>(out + (size_t)blockIdx.x * DIM);

    float4 v0 = xr[t];
    float4 v1 = xr[t + TPB];
    float4 v2 = xr[t + 2 * TPB];
    float4 v3 = xr[t + 3 * TPB];

    if (t == 0) s_cnt[0] = 0;
    if (t < 32) s_hist[t] = 0;           // pre-zeroed for first histogram pass

    // ---- stage A (one barrier): block max(|x|) + dual anchor counts ----
    float m = fabsf(v0.x);
    unsigned p = 0;
    #define MC(e) { float av = fabsf(e); m = fmaxf(m, av); \
                    if (av > BLO_A) p += 65536u; if (av > BHI_A) p += 1u; }
    MC(v0.y) MC(v0.z) MC(v0.w)
    MC(v1.x) MC(v1.y) MC(v1.z) MC(v1.w)
    MC(v2.x) MC(v2.y) MC(v2.z) MC(v2.w)
    MC(v3.x) MC(v3.y) MC(v3.z) MC(v3.w)
    { float av0 = fabsf(v0.x); if (av0 > BLO_A) p += 65536u; if (av0 > BHI_A) p += 1u; }
    #undef MC
    #pragma unroll
    for (int o = 16; o; o >>= 1) m = fmaxf(m, __shfl_xor_sync(0xFFFFFFFFu, m, o));
    p = __reduce_add_sync(0xFFFFFFFFu, p);
    if (lane == 0) { s_pack[wid] = p; s_wmax[wid] = m; }
    __syncthreads();
    unsigned totA = 0; float maxv = s_wmax[0];
    #pragma unroll
    for (int w = 0; w < NWARP; w++) { totA += s_pack[w]; maxv = fmaxf(maxv, s_wmax[w]); }
    const int cLoA = (int)(totA >> 16), cHiA = (int)(totA & 0xFFFFu);

    // ---- bracket init: invariant count(>lo)=cLo >= K > cHi=count(>hi) ----
    float lo, hi; int cLo, cHi;
    if (cLoA >= KSEL && KSEL > cHiA) { lo = BLO_A; hi = BHI_A; cLo = cLoA; cHi = cHiA; }
    else if (cHiA >= KSEL)           { lo = BHI_A; hi = maxv;  cLo = cHiA; cHi = 0;    }
    else                             { lo = -1.0f; hi = BLO_A; cLo = DIM;  cHi = cLoA; }

    // block-wide count(|x| > thr); two barriers (WAR-safe), rare path only
    auto countAbove = [&](float thr) -> int {
        int c = 0;
        #define CA(e) c += fabsf(e) > thr;
        CA(v0.x) CA(v0.y) CA(v0.z) CA(v0.w)
        CA(v1.x) CA(v1.y) CA(v1.z) CA(v1.w)
        CA(v2.x) CA(v2.y) CA(v2.z) CA(v2.w)
        CA(v3.x) CA(v3.y) CA(v3.z) CA(v3.w)
        #undef CA
        unsigned r = __reduce_add_sync(0xFFFFFFFFu, (unsigned)c);
        if (lane == 0) s_pack[wid] = r;
        __syncthreads();
        unsigned tot = 0;
        #pragma unroll
        for (int w = 0; w < NWARP; w++) tot += s_pack[w];
        __syncthreads();
        return (int)tot;
    };

    // ---- rare fallback: bisect until candidate window fits comfortably ----
    int guard = 0;
    while ((cLo - cHi) > (MAXC - 64) && guard < 40) {
        float mid = 0.5f * (lo + hi);
        if (!(mid > lo && mid < hi)) break;   // degenerate (near-ties): accept window
        int c = countAbove(mid);
        if (c >= KSEL) { lo = mid; cLo = c; }
        else           { hi = mid; cHi = c; }
        guard++;
    }

    // ---- gather candidates in (lo, hi] ----
    if (t == 0) s_thr = hi;   // safety default (pathological truncation only)
    {
        float av;
        #define TRY_CAND(e) \
            av = fabsf(e); \
            if (av > lo && av <= hi) { int id = atomicAdd(&s_cnt[0], 1); if (id < MAXC) s_buf[0][id] = av; }
        TRY_CAND(v0.x) TRY_CAND(v0.y) TRY_CAND(v0.z) TRY_CAND(v0.w)
        TRY_CAND(v1.x) TRY_CAND(v1.y) TRY_CAND(v1.z) TRY_CAND(v1.w)
        TRY_CAND(v2.x) TRY_CAND(v2.y) TRY_CAND(v2.z) TRY_CAND(v2.w)
        TRY_CAND(v3.x) TRY_CAND(v3.y) TRY_CAND(v3.z) TRY_CAND(v3.w)
        #undef TRY_CAND
    }
    __syncthreads();

    int   c    = min(s_cnt[0], MAXC);
    int   nd   = KSEL - cHi;             // 1-based rank within candidate set
    float wlo  = lo, whi = hi;
    int   cur  = 0;

    // ---- histogram selection: 32-bin narrow until c <= SMALLC (typically 1 iter) ----
    int it = 0;
    while (c > SMALLC && it < 6) {
        int nxt = cur ^ 1;
        // phase 1: zero next counter (+hist for it>0)
        if (it > 0) { if (t < 32) s_hist[t] = 0; }
        if (t == 0) s_cnt[nxt] = 0;
        __syncthreads();
        // phase 2: histogram over current candidates
        float scale = 32.0f / (whi - wlo);
        for (int j = t; j < c; j += TPB) {
            int b = (int)((s_buf[cur][j] - wlo) * scale);
            b = min(31, max(0, b));
            atomicAdd(&s_hist[b], 1);
        }
        __syncthreads();
        // phase 3: warp 0 scans bins from the top, finds rank bin
        if (wid == 0) {
            int val = s_hist[31 - lane];
            int cum = val;
            #pragma unroll
            for (int o = 1; o < 32; o <<= 1) {
                int n = __shfl_up_sync(0xFFFFFFFFu, cum, o);
                if (lane >= o) cum += n;
            }
            unsigned bal = __ballot_sync(0xFFFFFFFFu, cum >= nd);
            int L = __ffs(bal) - 1;       // exists: total (lane31) = c >= nd
            if (lane == L) { s_selbin = 31 - L; s_need = nd - (cum - val); }
        }
        __syncthreads();
        // phase 4: compact rank-bin members into the other buffer
        int bsel = s_selbin;
        for (int j = t; j < c; j += TPB) {
            float v = s_buf[cur][j];
            int b = (int)((v - wlo) * scale);
            b = min(31, max(0, b));
            if (b == bsel) { int id = atomicAdd(&s_cnt[nxt], 1); if (id < MAXC) s_buf[nxt][id] = v; }
        }
        __syncthreads();
        float binw = (whi - wlo) * (1.0f / 32.0f);
        whi = wlo + (float)(bsel + 1) * binw;
        wlo = wlo + (float)bsel * binw;
        nd  = s_need;
        c   = min(s_cnt[nxt], MAXC);
        cur = nxt;
        it++;
    }

    // ---- exact select: nd-th largest among c (<= SMALLC) candidates ----
    for (int j = t; j < c; j += TPB) {
        float vj = s_buf[cur][j];
        int gt = 0, ge = 0;
        for (int i = 0; i < c; i++) {
            float vi = s_buf[cur][i];    // smem broadcast
            gt += vi > vj;
            ge += vi >= vj;
        }
        if (gt < nd && nd <= ge) s_thr = vj;   // matching writers all write the same value
    }
    __syncthreads();
    const float thr   = s_thr;
    const float bias5 = -5.0f * thr;     // z/2 for sigmoid-via-tanh

    // ---- fused epilogue: out = x * (0.5 + 0.5*tanh(5*(|x|-thr))) ----
    auto mask1 = [&](float xv) -> float {
        float z = fmaf(5.0f, fabsf(xv), bias5);
        float th;
        asm("tanh.approx.f32 %0, %1;" : "=f"(th) : "f"(z));
        return xv * fmaf(0.5f, th, 0.5f);
    };
    float4 o0, o1, o2, o3;
    o0.x = mask1(v0.x); o0.y = mask1(v0.y); o0.z = mask1(v0.z); o0.w = mask1(v0.w);
    o1.x = mask1(v1.x); o1.y = mask1(v1.y); o1.z = mask1(v1.z); o1.w = mask1(v1.w);
    o2.x = mask1(v2.x); o2.y = mask1(v2.y); o2.z = mask1(v2.z); o2.w = mask1(v2.w);
    o3.x = mask1(v3.x); o3.y = mask1(v3.y); o3.z = mask1(v3.z); o3.w = mask1(v3.w);
    orow[t]           = o0;
    orow[t + TPB]     = o1;
    orow[t + 2 * TPB] = o2;
    orow[t + 3 * TPB] = o3;
}

extern "C" void kernel_launch(void* const* d_in, const int* in_sizes, int n_in,
                              void* d_out, int out_size) {
    const float* x = (const float*)d_in[0];
    float* out = (float*)d_out;
    const int rows = in_sizes[0] / DIM;   // 4 * 2048 = 8192 rows
    sparsify_kernel<<<rows, TPB>>>(x, out);
}

// round 9
// speedup vs baseline: 1.4046x; 1.0446x over previous
#include <cuda_runtime.h>

#define TPB   256
#define DIM   4096
#define KSEL  409
#define NWARP (TPB / 32)
#define MAXC  512

// 256 exact power-of-two bins over (1.5, 2.0]: bin = (|x|-1.5)*512, computed as
// fma(|x|, 512, -768) which is EXACT for |x| in (1.5, 2) -> deterministic binning.
// Values >= 2.0 saturate into bin 255 (overflow bin), so the top-down cumulative
// directly gives count(|x| >= bin lower edge) and the global rank needs no
// separate tail count. For N(0,1) rows: count(|x|>1.5)~547 (rank 409 inside at
// +6.3 sigma), count(|x|>=2.0)~186 (16 sigma below 409) -> bins [0,255) hold the
// threshold w.p. ~1-1e-10 per row. Anything else takes the generic fallback.
__global__ __launch_bounds__(TPB) void sparsify_kernel(const float* __restrict__ x,
                                                       float* __restrict__ out) {
    __shared__ int      s_hist[256];
    __shared__ unsigned s_w[NWARP];
    __shared__ float    s_wf[NWARP];
    __shared__ float    s_memb[MAXC];
    __shared__ int      s_cnt;
    __shared__ int      s_selbin, s_need;
    __shared__ float    s_thr;

    const int t    = threadIdx.x;
    const int lane = t & 31;
    const int wid  = t >> 5;

    const float4* xr   = reinterpret_cast<const float4*>(x + (size_t)blockIdx.x * DIM);
    float4*       orow = reinterpret_cast<float4*>(out + (size_t)blockIdx.x * DIM);

    float4 v0 = xr[t];
    float4 v1 = xr[t + TPB];
    float4 v2 = xr[t + 2 * TPB];
    float4 v3 = xr[t + 3 * TPB];

    s_hist[t] = 0;
    if (t == 0) { s_cnt = 0; s_selbin = 255; s_need = 1; s_thr = 1.645f; }
    __syncthreads();                                   // B1

    // ---- stage A: one-pass exact histogram ----
    #define HC(e) { float d = fmaf(fabsf(e), 512.0f, -768.0f); \
                    int b = min(__float2int_rz(d), 255); \
                    if (d > 0.0f) atomicAdd(&s_hist[b], 1); }
    HC(v0.x) HC(v0.y) HC(v0.z) HC(v0.w)
    HC(v1.x) HC(v1.y) HC(v1.z) HC(v1.w)
    HC(v2.x) HC(v2.y) HC(v2.z) HC(v2.w)
    HC(v3.x) HC(v3.y) HC(v3.z) HC(v3.w)
    #undef HC
    __syncthreads();                                   // B2

    // ---- warp 0: top-down scan of 256 bins -> rank bin + local rank ----
    if (wid == 0) {
        const int base = 255 - 8 * lane;               // lane0: bins 255..248, ...
        int h[8]; int lsum = 0;
        #pragma unroll
        for (int k = 0; k < 8; k++) { h[k] = s_hist[base - k]; lsum += h[k]; }
        int cum = lsum;
        #pragma unroll
        for (int o = 1; o < 32; o <<= 1) {
            int n = __shfl_up_sync(0xFFFFFFFFu, cum, o);
            if (lane >= o) cum += n;
        }
        unsigned bal = __ballot_sync(0xFFFFFFFFu, cum >= KSEL);
        if (bal) {
            int L = __ffs(bal) - 1;
            if (lane == L) {
                int ca = cum - lsum;                   // count strictly above this lane's bins
                int sel = 255, r = 1;
                #pragma unroll
                for (int k = 0; k < 8; k++) {
                    if (ca + h[k] >= KSEL) { sel = base - k; r = KSEL - ca; break; }
                    ca += h[k];
                }
                s_selbin = sel; s_need = r;
            }
        }
        // bal == 0 -> s_selbin stays 255 -> fallback
    }
    __syncthreads();                                   // B3

    const int sb = s_selbin;                           // uniform across CTA
    int nd;
    if (sb < 255) {
        // ---- gather rank-bin members (membership recomputed IDENTICALLY) ----
        nd = s_need;
        #define TG(e) { float d = fmaf(fabsf(e), 512.0f, -768.0f); \
                        if (d > 0.0f && __float2int_rz(d) == sb) { \
                            int id = atomicAdd(&s_cnt, 1); \
                            if (id < MAXC) s_memb[id] = fabsf(e); } }
        TG(v0.x) TG(v0.y) TG(v0.z) TG(v0.w)
        TG(v1.x) TG(v1.y) TG(v1.z) TG(v1.w)
        TG(v2.x) TG(v2.y) TG(v2.z) TG(v2.w)
        TG(v3.x) TG(v3.y) TG(v3.z) TG(v3.w)
        #undef TG
    } else {
        // ---- generic fallback: exact bisection (CTA-uniform, ~never taken) ----
        float m = fabsf(v0.x);
        m = fmaxf(m, fabsf(v0.y)); m = fmaxf(m, fabsf(v0.z)); m = fmaxf(m, fabsf(v0.w));
        m = fmaxf(m, fabsf(v1.x)); m = fmaxf(m, fabsf(v1.y)); m = fmaxf(m, fabsf(v1.z)); m = fmaxf(m, fabsf(v1.w));
        m = fmaxf(m, fabsf(v2.x)); m = fmaxf(m, fabsf(v2.y)); m = fmaxf(m, fabsf(v2.z)); m = fmaxf(m, fabsf(v2.w));
        m = fmaxf(m, fabsf(v3.x)); m = fmaxf(m, fabsf(v3.y)); m = fmaxf(m, fabsf(v3.z)); m = fmaxf(m, fabsf(v3.w));
        #pragma unroll
        for (int o = 16; o; o >>= 1) m = fmaxf(m, __shfl_xor_sync(0xFFFFFFFFu, m, o));
        if (lane == 0) s_wf[wid] = m;
        __syncthreads();
        float maxv = s_wf[0];
        #pragma unroll
        for (int w = 1; w < NWARP; w++) maxv = fmaxf(maxv, s_wf[w]);
        __syncthreads();

        float lo = -1.0f, hi = maxv;
        int cLo = DIM, cHi = 0, guard = 0;
        while ((cLo - cHi) > (MAXC - 64) && guard < 40) {
            float mid = 0.5f * (lo + hi);
            if (!(mid > lo && mid < hi)) break;        // degenerate (ties)
            int cc = 0;
            #define CA(e) cc += fabsf(e) > mid;
            CA(v0.x) CA(v0.y) CA(v0.z) CA(v0.w)
            CA(v1.x) CA(v1.y) CA(v1.z) CA(v1.w)
            CA(v2.x) CA(v2.y) CA(v2.z) CA(v2.w)
            CA(v3.x) CA(v3.y) CA(v3.z) CA(v3.w)
            #undef CA
            unsigned r = __reduce_add_sync(0xFFFFFFFFu, (unsigned)cc);
            if (lane == 0) s_w[wid] = r;
            __syncthreads();
            unsigned tot = 0;
            #pragma unroll
            for (int w = 0; w < NWARP; w++) tot += s_w[w];
            __syncthreads();
            if ((int)tot >= KSEL) { lo = mid; cLo = (int)tot; }
            else                  { hi = mid; cHi = (int)tot; }
            guard++;
        }
        if (t == 0) s_cnt = 0;
        __syncthreads();
        #define TG2(e) { float av = fabsf(e); \
                         if (av > lo && av <= hi) { int id = atomicAdd(&s_cnt, 1); \
                             if (id < MAXC) s_memb[id] = av; } }
        TG2(v0.x) TG2(v0.y) TG2(v0.z) TG2(v0.w)
        TG2(v1.x) TG2(v1.y) TG2(v1.z) TG2(v1.w)
        TG2(v2.x) TG2(v2.y) TG2(v2.z) TG2(v2.w)
        TG2(v3.x) TG2(v3.y) TG2(v3.z) TG2(v3.w)
        #undef TG2
        nd = KSEL - cHi;
    }
    __syncthreads();                                   // B4

    // ---- exact select: nd-th largest among c members (typically c ~ 2-4) ----
    const int c = min(s_cnt, MAXC);
    for (int j = t; j < c; j += TPB) {
        float vj = s_memb[j];
        int gt = 0, ge = 0;
        for (int i = 0; i < c; i++) {
            float vi = s_memb[i];
            gt += vi > vj;
            ge += vi >= vj;
        }
        if (gt < nd && nd <= ge) s_thr = vj;           // matching writers write same value
    }
    __syncthreads();                                   // B5

    const float thr   = s_thr;
    const float bias5 = -5.0f * thr;

    // ---- fused epilogue: out = x * (0.5 + 0.5*tanh(5*(|x|-thr))) ----
    auto mask1 = [&](float xv) -> float {
        float z = fmaf(5.0f, fabsf(xv), bias5);
        float th;
        asm("tanh.approx.f32 %0, %1;" : "=f"(th) : "f"(z));
        return xv * fmaf(0.5f, th, 0.5f);
    };
    float4 o0, o1, o2, o3;
    o0.x = mask1(v0.x); o0.y = mask1(v0.y); o0.z = mask1(v0.z); o0.w = mask1(v0.w);
    o1.x = mask1(v1.x); o1.y = mask1(v1.y); o1.z = mask1(v1.z); o1.w = mask1(v1.w);
    o2.x = mask1(v2.x); o2.y = mask1(v2.y); o2.z = mask1(v2.z); o2.w = mask1(v2.w);
    o3.x = mask1(v3.x); o3.y = mask1(v3.y); o3.z = mask1(v3.z); o3.w = mask1(v3.w);
    orow[t]           = o0;
    orow[t + TPB]     = o1;
    orow[t + 2 * TPB] = o2;
    orow[t + 3 * TPB] = o3;
}

extern "C" void kernel_launch(void* const* d_in, const int* in_sizes, int n_in,
                              void* d_out, int out_size) {
    const float* x = (const float*)d_in[0];
    float* out = (float*)d_out;
    const int rows = in_sizes[0] / DIM;   // 4 * 2048 = 8192 rows
    sparsify_kernel<<<rows, TPB>>>(x, out);
}

// round 10
// speedup vs baseline: 1.6927x; 1.2051x over previous
#include <cuda_runtime.h>

#define TPB   256
#define DIM   4096
#define KSEL  409
#define NWARP (TPB / 32)
#define MAXC  512

// 256 exact power-of-two bins over (1.5, 2.0]: bin = (|x|-1.5)*512 via
// fma(|x|,512,-768), EXACT for |x| in (1.5,2) -> deterministic membership.
// >=2.0 saturates into overflow bin 255, so the top-down cumulative equals
// count(|x| >= bin lower edge); no separate tail count needed. Non-Gaussian
// rows (rank bin not found below 255) take the generic bisection fallback.
//
// Row is staged in SMEM so the 16 values are NOT register-resident across the
// serial hist->scan->gather->select phases: regs ~32 -> 8 CTAs/SM.
__global__ __launch_bounds__(TPB, 8) void sparsify_kernel(const float* __restrict__ x,
                                                          float* __restrict__ out) {
    __shared__ float    s_row[DIM];            // 16 KB staged row
    __shared__ int      s_hist[256];
    __shared__ unsigned s_w[NWARP];
    __shared__ float    s_wf[NWARP];
    __shared__ float    s_memb[MAXC];
    __shared__ int      s_cnt;
    __shared__ int      s_selbin, s_need;
    __shared__ float    s_thr;

    const int t    = threadIdx.x;
    const int lane = t & 31;
    const int wid  = t >> 5;

    const float4* xr    = reinterpret_cast<const float4*>(x + (size_t)blockIdx.x * DIM);
    float4*       orow  = reinterpret_cast<float4*>(out + (size_t)blockIdx.x * DIM);
    float4*       srow4 = reinterpret_cast<float4*>(s_row);

    s_hist[t] = 0;
    if (t == 0) { s_cnt = 0; s_selbin = 255; s_need = 1; s_thr = 1.645f; }
    __syncthreads();                                   // B1

    // ---- pass 1: load -> stage to smem -> histogram (values transient) ----
    #pragma unroll
    for (int u = 0; u < 4; u++) {
        float4 v = xr[t + u * TPB];
        srow4[t + u * TPB] = v;
        #define HC(e) { float d = fmaf(fabsf(e), 512.0f, -768.0f); \
                        int b = min(__float2int_rz(d), 255); \
                        if (d > 0.0f) atomicAdd(&s_hist[b], 1); }
        HC(v.x) HC(v.y) HC(v.z) HC(v.w)
        #undef HC
    }
    __syncthreads();                                   // B2

    // ---- warp 0: top-down scan of 256 bins -> rank bin + local rank ----
    if (wid == 0) {
        const int base = 255 - 8 * lane;               // lane0: bins 255..248, ...
        int h[8]; int lsum = 0;
        #pragma unroll
        for (int k = 0; k < 8; k++) { h[k] = s_hist[base - k]; lsum += h[k]; }
        int cum = lsum;
        #pragma unroll
        for (int o = 1; o < 32; o <<= 1) {
            int n = __shfl_up_sync(0xFFFFFFFFu, cum, o);
            if (lane >= o) cum += n;
        }
        unsigned bal = __ballot_sync(0xFFFFFFFFu, cum >= KSEL);
        if (bal) {
            int L = __ffs(bal) - 1;
            if (lane == L) {
                int ca = cum - lsum;                   // count strictly above lane's bins
                int sel = 255, r = 1;
                #pragma unroll
                for (int k = 0; k < 8; k++) {
                    if (ca + h[k] >= KSEL) { sel = base - k; r = KSEL - ca; break; }
                    ca += h[k];
                }
                s_selbin = sel; s_need = r;
            }
        }
        // bal == 0 -> s_selbin stays 255 -> fallback
    }
    __syncthreads();                                   // B3

    const int sb = s_selbin;                           // uniform across CTA
    int nd;
    if (sb < 255) {
        // ---- gather rank-bin members from smem (identical bin recompute) ----
        nd = s_need;
        #pragma unroll
        for (int u = 0; u < 4; u++) {
            float4 v = srow4[t + u * TPB];
            #define TG(e) { float d = fmaf(fabsf(e), 512.0f, -768.0f); \
                            if (d > 0.0f && __float2int_rz(d) == sb) { \
                                int id = atomicAdd(&s_cnt, 1); \
                                if (id < MAXC) s_memb[id] = fabsf(e); } }
            TG(v.x) TG(v.y) TG(v.z) TG(v.w)
            #undef TG
        }
    } else {
        // ---- generic fallback: exact bisection over smem row (~never taken) ----
        float m = 0.0f;
        #pragma unroll
        for (int u = 0; u < 4; u++) {
            float4 v = srow4[t + u * TPB];
            m = fmaxf(m, fmaxf(fmaxf(fabsf(v.x), fabsf(v.y)),
                               fmaxf(fabsf(v.z), fabsf(v.w))));
        }
        #pragma unroll
        for (int o = 16; o; o >>= 1) m = fmaxf(m, __shfl_xor_sync(0xFFFFFFFFu, m, o));
        if (lane == 0) s_wf[wid] = m;
        __syncthreads();
        float maxv = s_wf[0];
        #pragma unroll
        for (int w = 1; w < NWARP; w++) maxv = fmaxf(maxv, s_wf[w]);
        __syncthreads();

        float lo = -1.0f, hi = maxv;
        int cLo = DIM, cHi = 0, guard = 0;
        while ((cLo - cHi) > (MAXC - 64) && guard < 40) {
            float mid = 0.5f * (lo + hi);
            if (!(mid > lo && mid < hi)) break;        // degenerate (ties)
            int cc = 0;
            #pragma unroll
            for (int u = 0; u < 4; u++) {
                float4 v = srow4[t + u * TPB];
                cc += fabsf(v.x) > mid; cc += fabsf(v.y) > mid;
                cc += fabsf(v.z) > mid; cc += fabsf(v.w) > mid;
            }
            unsigned r = __reduce_add_sync(0xFFFFFFFFu, (unsigned)cc);
            if (lane == 0) s_w[wid] = r;
            __syncthreads();
            unsigned tot = 0;
            #pragma unroll
            for (int w = 0; w < NWARP; w++) tot += s_w[w];
            __syncthreads();
            if ((int)tot >= KSEL) { lo = mid; cLo = (int)tot; }
            else                  { hi = mid; cHi = (int)tot; }
            guard++;
        }
        if (t == 0) s_cnt = 0;
        __syncthreads();
        #pragma unroll
        for (int u = 0; u < 4; u++) {
            float4 v = srow4[t + u * TPB];
            #define TG2(e) { float av = fabsf(e); \
                             if (av > lo && av <= hi) { int id = atomicAdd(&s_cnt, 1); \
                                 if (id < MAXC) s_memb[id] = av; } }
            TG2(v.x) TG2(v.y) TG2(v.z) TG2(v.w)
            #undef TG2
        }
        nd = KSEL - cHi;
    }
    __syncthreads();                                   // B4

    // ---- exact select: nd-th largest among c members (typically c ~ 2-4) ----
    const int c = min(s_cnt, MAXC);
    for (int j = t; j < c; j += TPB) {
        float vj = s_memb[j];
        int gt = 0, ge = 0;
        for (int i = 0; i < c; i++) {
            float vi = s_memb[i];
            gt += vi > vj;
            ge += vi >= vj;
        }
        if (gt < nd && nd <= ge) s_thr = vj;           // matching writers write same value
    }
    __syncthreads();                                   // B5

    const float thr   = s_thr;
    const float bias5 = -5.0f * thr;

    // ---- fused epilogue: out = x * (0.5 + 0.5*tanh(5*(|x|-thr))) ----
    #pragma unroll
    for (int u = 0; u < 4; u++) {
        float4 v = srow4[t + u * TPB];
        float4 o;
        #define MK(dst, xv) { float z = fmaf(5.0f, fabsf(xv), bias5); float th; \
                              asm("tanh.approx.f32 %0, %1;" : "=f"(th) : "f"(z)); \
                              dst = (xv) * fmaf(0.5f, th, 0.5f); }
        MK(o.x, v.x) MK(o.y, v.y) MK(o.z, v.z) MK(o.w, v.w)
        #undef MK
        orow[t + u * TPB] = o;
    }
}

extern "C" void kernel_launch(void* const* d_in, const int* in_sizes, int n_in,
                              void* d_out, int out_size) {
    const float* x = (const float*)d_in[0];
    float* out = (float*)d_out;
    const int rows = in_sizes[0] / DIM;   // 4 * 2048 = 8192 rows
    sparsify_kernel<<<rows, TPB>>>(x, out);
}